// round 4
// baseline (speedup 1.0000x reference)
#include <cuda_runtime.h>

// ---------------------------------------------------------------------------
// FFB encoder, fp32 baseline tuned for sm_103a:
//  - register-tiled SMEM GEMMs (128x128 per level, x2)
//  - packed fma.rn.f32x2 (2x fp32 FMA rate on Blackwell; ptxas never emits it)
//  - weights staged per-level into SMEM (L2-resident across the grid)
// ---------------------------------------------------------------------------

#define HID      128
#define LVL      7
#define TP       128      // points per block
#define NTHREADS 256
#define WS       132      // padded SMEM row stride (floats)
#define W0_SINE  56.0f
#define TWO_PIf  6.28318530717958647692f

typedef unsigned long long u64;

__device__ __forceinline__ u64 pk2(float lo, float hi) {
    u64 r;
    asm("mov.b64 %0, {%1, %2};" : "=l"(r)
        : "r"(__float_as_uint(lo)), "r"(__float_as_uint(hi)));
    return r;
}
__device__ __forceinline__ void upk2(u64 v, float& lo, float& hi) {
    unsigned int a, b;
    asm("mov.b64 {%0, %1}, %2;" : "=r"(a), "=r"(b) : "l"(v));
    lo = __uint_as_float(a);
    hi = __uint_as_float(b);
}
__device__ __forceinline__ void fma2(u64& d, u64 a, u64 b) {
    asm("fma.rn.f32x2 %0, %1, %2, %0;" : "+l"(d) : "l"(a), "l"(b));
}

// 256 threads cooperatively copy a 128x128 fp32 weight matrix (row-major,
// rows = output unit h, cols = k) into SMEM with padded stride WS.
__device__ __forceinline__ void load_weight(float* __restrict__ dst,
                                            const float* __restrict__ src,
                                            int tid) {
    const int row  = tid >> 1;
    const int half = (tid & 1) * 64;
    const float4* s = reinterpret_cast<const float4*>(src + row * HID + half);
    float4*       d = reinterpret_cast<float4*>(dst + row * WS + half);
#pragma unroll
    for (int v = 0; v < 16; ++v) d[v] = s[v];
}

// Y[n][h] = sum_k xs[n][k] * ws[h][k] for the thread's 8x8 tile.
// Accumulators are f32x2 pairs: acc[i][j2] = { y(n_i, tc+32*j2), y(n_i, tc+32*j2+16) }
__device__ __forceinline__ void gemm_tile(const float* __restrict__ xs,
                                          const float* __restrict__ ws,
                                          int tr, int tc, u64 acc[8][4]) {
#pragma unroll
    for (int i = 0; i < 8; ++i)
#pragma unroll
        for (int j = 0; j < 4; ++j) acc[i][j] = 0ULL;

#pragma unroll 2
    for (int k = 0; k < HID; k += 4) {
        float a[8][4], b[8][4];
#pragma unroll
        for (int i = 0; i < 8; ++i)
            *reinterpret_cast<float4*>(a[i]) =
                *reinterpret_cast<const float4*>(xs + (tr + 16 * i) * WS + k);
#pragma unroll
        for (int j = 0; j < 8; ++j)
            *reinterpret_cast<float4*>(b[j]) =
                *reinterpret_cast<const float4*>(ws + (tc + 16 * j) * WS + k);
#pragma unroll
        for (int c = 0; c < 4; ++c) {
            u64 b2[4];
#pragma unroll
            for (int j2 = 0; j2 < 4; ++j2)
                b2[j2] = pk2(b[2 * j2][c], b[2 * j2 + 1][c]);
#pragma unroll
            for (int i = 0; i < 8; ++i) {
                u64 aa = pk2(a[i][c], a[i][c]);
#pragma unroll
                for (int j2 = 0; j2 < 4; ++j2) fma2(acc[i][j2], aa, b2[j2]);
            }
        }
    }
}

extern __shared__ float smem[];

__global__ __launch_bounds__(NTHREADS, 1)
void ffb_encoder_kernel(const float* __restrict__ in_pos,
                        const float* __restrict__ grid_feats,
                        const float* __restrict__ ffn_A,
                        const float* __restrict__ ffn_sigma,
                        const float* __restrict__ W0,
                        const float* __restrict__ b0,
                        const float* __restrict__ W_mid,
                        const float* __restrict__ b_mid,
                        const float* __restrict__ W_high,
                        const float* __restrict__ b_high,
                        float* __restrict__ out) {
    float* xs  = smem;                  // TP * WS
    float* ws  = xs + TP * WS;          // HID * WS
    float* gs  = ws + HID * WS;         // TP * 14
    float* As  = gs + TP * 14;          // LVL * 2 * HID (pre-scaled by 2*pi*sigma)
    float* bms = As + LVL * 2 * HID;    // LVL * HID
    float* bhs = bms + LVL * HID;       // LVL * HID
    float* ps  = bhs + LVL * HID;       // TP * 3

    const int tid = threadIdx.x;
    const int n0  = blockIdx.x * TP;
    const int tr  = tid >> 4;   // 0..15, point-group
    const int tc  = tid & 15;   // 0..15, hidden-group

    // ------------------------- setup: stage to SMEM -------------------------
    for (int idx = tid; idx < TP * 14; idx += NTHREADS) {
        int p = idx / 14, c = idx - p * 14;
        gs[idx] = grid_feats[(n0 + p) * 17 + 3 + c];
    }
    for (int idx = tid; idx < TP * 3; idx += NTHREADS) {
        int p = idx / 3, d = idx - p * 3;
        float v = in_pos[(n0 + p) * 3 + d];
        ps[idx]  = v;
        out[(size_t)(n0 + p) * 131 + d] = (v + 1.0f) * 0.5f;   // pos01
    }
    for (int idx = tid; idx < LVL * 2 * HID; idx += NTHREADS) {
        int l = idx / (2 * HID);
        As[idx] = ffn_A[idx] * ffn_sigma[l] * TWO_PIf;
    }
    for (int idx = tid; idx < LVL * HID; idx += NTHREADS) {
        bms[idx] = b_mid[idx];
        bhs[idx] = b_high[idx];
    }
    // stage W0/b0 into ws (temporarily) as [h]{w0,w1,w2,b}
    if (tid < HID) {
        ws[tid * 4 + 0] = W0[tid * 3 + 0];
        ws[tid * 4 + 1] = W0[tid * 3 + 1];
        ws[tid * 4 + 2] = W0[tid * 3 + 2];
        ws[tid * 4 + 3] = b0[tid];
    }
    __syncthreads();

    // ------------------------- first SIREN layer ---------------------------
#pragma unroll
    for (int i = 0; i < 8; ++i) {
        int n = tr + 16 * i;
        float p0 = ps[n * 3 + 0], p1 = ps[n * 3 + 1], p2 = ps[n * 3 + 2];
#pragma unroll
        for (int j = 0; j < 8; ++j) {
            int h = tc + 16 * j;
            const float* w = ws + h * 4;
            float u = fmaf(p0, w[0], fmaf(p1, w[1], fmaf(p2, w[2], w[3])));
            xs[n * WS + h] = __sinf(W0_SINE * u);
        }
    }

    float buf[8][8];
#pragma unroll
    for (int i = 0; i < 8; ++i)
#pragma unroll
        for (int j = 0; j < 8; ++j) buf[i][j] = 0.0f;

    u64 acc[8][4];

    // ------------------------------ level loop -----------------------------
    for (int l = 0; l < LVL; ++l) {
        __syncthreads();                          // prior ws readers done
        load_weight(ws, W_mid + l * HID * HID, tid);
        __syncthreads();

        gemm_tile(xs, ws, tr, tc, acc);           // t = x @ Wm^T
        __syncthreads();                          // all xs reads done

        // x = sin(2*pi*A . g) + sin(56*(t + bm))   (residual), write back
#pragma unroll
        for (int i = 0; i < 8; ++i) {
            int n = tr + 16 * i;
            float g0 = gs[n * 14 + 2 * l];
            float g1 = gs[n * 14 + 2 * l + 1];
#pragma unroll
            for (int j2 = 0; j2 < 4; ++j2) {
                float v0, v1;
                upk2(acc[i][j2], v0, v1);
                int h0 = tc + 32 * j2, h1 = h0 + 16;
                float gr0 = sinf(fmaf(g0, As[(2 * l) * HID + h0],
                                      g1 * As[(2 * l + 1) * HID + h0]));
                float gr1 = sinf(fmaf(g0, As[(2 * l) * HID + h1],
                                      g1 * As[(2 * l + 1) * HID + h1]));
                xs[n * WS + h0] = gr0 + __sinf(W0_SINE * (v0 + bms[l * HID + h0]));
                xs[n * WS + h1] = gr1 + __sinf(W0_SINE * (v1 + bms[l * HID + h1]));
            }
        }
        __syncthreads();                          // xs writes visible, ws free
        load_weight(ws, W_high + l * HID * HID, tid);
        __syncthreads();

        gemm_tile(xs, ws, tr, tc, acc);           // u = x @ Wh^T

        // buf += sin(56*(u + bh))   (stays in registers across levels)
#pragma unroll
        for (int i = 0; i < 8; ++i) {
#pragma unroll
            for (int j2 = 0; j2 < 4; ++j2) {
                float v0, v1;
                upk2(acc[i][j2], v0, v1);
                int h0 = tc + 32 * j2, h1 = h0 + 16;
                buf[i][2 * j2]     += __sinf(W0_SINE * (v0 + bhs[l * HID + h0]));
                buf[i][2 * j2 + 1] += __sinf(W0_SINE * (v1 + bhs[l * HID + h1]));
            }
        }
        // top-of-loop __syncthreads() orders ws reuse for next level
    }

    // ------------------------------- epilogue ------------------------------
    const float inv = 1.0f / 7.0f;
#pragma unroll
    for (int i = 0; i < 8; ++i) {
        size_t n = (size_t)(n0 + tr + 16 * i);
#pragma unroll
        for (int j = 0; j < 8; ++j) {
            int h = tc + 16 * j;
            out[n * 131 + 3 + h] = buf[i][j] * inv;
        }
    }
}

extern "C" void kernel_launch(void* const* d_in, const int* in_sizes, int n_in,
                              void* d_out, int out_size) {
    const float* in_pos     = (const float*)d_in[0];
    const float* grid_feats = (const float*)d_in[1];
    const float* ffn_A      = (const float*)d_in[2];
    const float* ffn_sigma  = (const float*)d_in[3];
    const float* W0         = (const float*)d_in[4];
    const float* b0         = (const float*)d_in[5];
    const float* W_mid      = (const float*)d_in[6];
    const float* b_mid      = (const float*)d_in[7];
    const float* W_high     = (const float*)d_in[8];
    const float* b_high     = (const float*)d_in[9];
    float* out = (float*)d_out;

    const int N       = in_sizes[0] / 3;   // 131072
    const int nblocks = N / TP;            // 1024

    const size_t smem_bytes =
        (size_t)(TP * WS + HID * WS + TP * 14 + LVL * 2 * HID +
                 2 * LVL * HID + TP * 3) * sizeof(float);   // ~158 KB

    // Idempotent, called every time (deterministic; legal during graph capture).
    cudaFuncSetAttribute(ffb_encoder_kernel,
                         cudaFuncAttributeMaxDynamicSharedMemorySize,
                         (int)smem_bytes);

    ffb_encoder_kernel<<<nblocks, NTHREADS, smem_bytes>>>(
        in_pos, grid_feats, ffn_A, ffn_sigma, W0, b0,
        W_mid, b_mid, W_high, b_high, out);
}